// round 15
// baseline (speedup 1.0000x reference)
#include <cuda_runtime.h>
#include <cuda_bf16.h>
#include <cstdint>

// fid[p] = clip( (va.vb)^2 / (|va|^2 |vb|^2), 0, 1 )
// va = tanh( relu(xa @ W1 + b1) @ W2 + b2 )   (quantum circuit is unitary -> cancels)
// GEMM1 via mma.sync m16n8k16 bf16 split hi/lo (3 MMAs). M=128/block, 8 warps, 32x32 tiles.
// A staged as RAW FP32 via cp.async (no LDG/convert/STS round-trip); hi/lo split happens in
// registers at fragment-load time. B tiles prepass-converted to smem images, contiguous cp.async.

#define KDIM   784
#define KC     16
#define NCHUNK 49
#define ASTR96 96      // A row stride bytes: 16 fp32 (64 B) + 32 pad -> quadrant-rotating, conflict-free
#define BSTRE  24      // B row stride in uint16 elems (48 B)
#define HSTR   66
#define BTILE  6144    // per-chunk B image: 3072 B hi + 3072 B lo

__device__ __align__(16) uint8_t g_W1B[NCHUNK * BTILE];

#define MMA(d, a, b) asm volatile( \
    "mma.sync.aligned.m16n8k16.row.col.f32.bf16.bf16.f32 " \
    "{%0,%1,%2,%3}, {%4,%5,%6,%7}, {%8,%9}, {%0,%1,%2,%3};" \
    : "+f"(d[0]), "+f"(d[1]), "+f"(d[2]), "+f"(d[3]) \
    : "r"(a[0]), "r"(a[1]), "r"(a[2]), "r"(a[3]), "r"(b[0]), "r"(b[1]))

__device__ __forceinline__ uint32_t bf2u(__nv_bfloat162 v) { return *(uint32_t*)&v; }

__device__ __forceinline__ uint32_t hi2(float x, float y, uint32_t& lo) {
    __nv_bfloat162 h = __float22bfloat162_rn(make_float2(x, y));
    __nv_bfloat162 l = __float22bfloat162_rn(make_float2(
        x - __bfloat162float(h.x), y - __bfloat162float(h.y)));
    lo = bf2u(l);
    return bf2u(h);
}

// float2 -> (hi bf16x2, lo bf16x2)
__device__ __forceinline__ uint32_t cvthl(float2 f, uint32_t& lo) {
    return hi2(f.x, f.y, lo);
}

__device__ __forceinline__ void cp16(uint32_t dst, const void* src) {
    asm volatile("cp.async.ca.shared.global [%0], [%1], 16;" :: "r"(dst), "l"(src));
}

// Per-chunk B tile images (identical to R10: row n = 16 bf16 at bytes [0,32) of a 48-B row).
__global__ void prep_w1(const float* __restrict__ W1) {
    int c = blockIdx.x;                 // 0..48
    int r = threadIdx.x;                // 0..255
    int n = r >> 2;
    int q = r & 3;
    int k = c * 16 + q * 4;
    float v0 = W1[(size_t)(k + 0) * 64 + n];
    float v1 = W1[(size_t)(k + 1) * 64 + n];
    float v2 = W1[(size_t)(k + 2) * 64 + n];
    float v3 = W1[(size_t)(k + 3) * 64 + n];
    uint32_t l0, l1;
    uint32_t h0 = hi2(v0, v1, l0);
    uint32_t h1 = hi2(v2, v3, l1);
    uint8_t* dst = g_W1B + (size_t)c * BTILE + n * 48 + q * 8;
    *(uint2*)dst          = make_uint2(h0, h1);
    *(uint2*)(dst + 3072) = make_uint2(l0, l1);
}

__global__ __launch_bounds__(256, 3)
void qcm_mma(const float* __restrict__ img_a,
             const float* __restrict__ img_b,
             const float* __restrict__ b1,
             const float* __restrict__ W2,
             const float* __restrict__ b2,
             float* __restrict__ out)
{
    __shared__ __align__(16) union {
        struct {
            uint8_t A[2][128 * ASTR96];    // 2 x 12288 B (fp32 rows, 96 B stride)
            uint8_t Bs[2][BTILE];          // 2 x 6144 B
        } m;                               // 36864 B
        struct {
            float H[128 * HSTR];
            float Vs[128 * 16];
            float ssq[128];
        } e;
    } sm;
    __shared__ float W2s[64 * 16];
    __shared__ float b1s[64];
    __shared__ float b2s[16];

    const int t    = threadIdx.x;
    const int lane = t & 31;
    const int wid  = t >> 5;
    const int wr   = wid >> 1;        // 0..3 : 32-row band
    const int wc   = wid & 1;         // 0..1 : 32-col half
    const int g    = lane >> 2;
    const int tig  = lane & 3;
    const int p0   = blockIdx.x * 64; // 64 pairs per block (128 rows)

    // params
    if (t < 64) b1s[t] = b1[t];
    if (t < 16) b2s[t] = b2[t];
    #pragma unroll
    for (int i = 0; i < 4; ++i) W2s[t + i * 256] = W2[t + i * 256];

    // A staging: 512 x 16B cp.async per chunk; thread t does 2 adjacent pieces of row t>>1
    const int arow = t >> 1;
    const int aq   = (t & 1) * 2;                 // piece index 0/2
    const float* abase = (arow < 64 ? img_a + (size_t)(p0 + arow) * KDIM
                                    : img_b + (size_t)(p0 + arow - 64) * KDIM) + aq * 4;
    const uint32_t sbA0 = (uint32_t)__cvta_generic_to_shared(sm.m.A[0]) + arow * ASTR96 + aq * 16;
    const uint32_t sbA1 = (uint32_t)__cvta_generic_to_shared(sm.m.A[1]) + arow * ASTR96 + aq * 16;
    const uint32_t sbB0 = (uint32_t)__cvta_generic_to_shared(sm.m.Bs[0]);
    const uint32_t sbB1 = (uint32_t)__cvta_generic_to_shared(sm.m.Bs[1]);

    float acc[2][4][4];
    #pragma unroll
    for (int mt = 0; mt < 2; ++mt)
        #pragma unroll
        for (int nt = 0; nt < 4; ++nt)
            #pragma unroll
            for (int j = 0; j < 4; ++j) acc[mt][nt][j] = 0.f;

    // ---- prologue: stage chunk 0 (all cp.async) ----
    {
        cp16(sbA0,      abase);
        cp16(sbA0 + 16, abase + 4);
        const uint8_t* src = g_W1B;
        cp16(sbB0 + t * 16, src + t * 16);
        if (t < 128) cp16(sbB0 + 4096 + t * 16, src + 4096 + t * 16);
        asm volatile("cp.async.commit_group;" ::: "memory");
        asm volatile("cp.async.wait_group 0;" ::: "memory");
    }
    __syncthreads();

    // ---- mainloop ----
    for (int c = 0; c < NCHUNK; ++c) {
        const int st = c & 1;
        const bool more = (c + 1 < NCHUNK);

        if (more) {
            const int k1 = (c + 1) * KC;
            const uint32_t dA = st ? sbA0 : sbA1;    // next buffer
            cp16(dA,      abase + k1);
            cp16(dA + 16, abase + k1 + 4);
            const uint8_t* src = g_W1B + (size_t)(c + 1) * BTILE;
            const uint32_t dB = st ? sbB0 : sbB1;
            cp16(dB + t * 16, src + t * 16);
            if (t < 128) cp16(dB + 4096 + t * 16, src + 4096 + t * 16);
            asm volatile("cp.async.commit_group;" ::: "memory");
        }

        const uint8_t*  As = sm.m.A[st];
        const uint16_t* Bh = (const uint16_t*)(sm.m.Bs[st]);
        const uint16_t* Bl = (const uint16_t*)(sm.m.Bs[st] + 3072);

        uint32_t bh[4][2], bl[4][2];
        #pragma unroll
        for (int nt = 0; nt < 4; ++nt) {
            int bb = (wc * 32 + nt * 8 + g) * BSTRE + 2 * tig;
            bh[nt][0] = *(const uint32_t*)&Bh[bb];
            bh[nt][1] = *(const uint32_t*)&Bh[bb + 8];
            bl[nt][0] = *(const uint32_t*)&Bl[bb];
            bl[nt][1] = *(const uint32_t*)&Bl[bb + 8];
        }

        #pragma unroll
        for (int mt = 0; mt < 2; ++mt) {
            const uint8_t* rbase = As + (wr * 32 + mt * 16 + g) * ASTR96 + tig * 8;
            float2 f0 = *(const float2*)(rbase);                    // row g,   k 2tig..2tig+1
            float2 f1 = *(const float2*)(rbase + 8 * ASTR96);       // row g+8
            float2 f2 = *(const float2*)(rbase + 32);               // row g,   k +8
            float2 f3 = *(const float2*)(rbase + 8 * ASTR96 + 32);  // row g+8, k +8
            uint32_t ah[4], al[4];
            ah[0] = cvthl(f0, al[0]);
            ah[1] = cvthl(f1, al[1]);
            ah[2] = cvthl(f2, al[2]);
            ah[3] = cvthl(f3, al[3]);
            #pragma unroll
            for (int nt = 0; nt < 4; ++nt) {
                MMA(acc[mt][nt], ah, bh[nt]);
                MMA(acc[mt][nt], ah, bl[nt]);
                MMA(acc[mt][nt], al, bh[nt]);
            }
        }

        asm volatile("cp.async.wait_group 0;" ::: "memory");
        __syncthreads();
    }

    // ---- epilogue: H = relu(acc + b1) into smem (fragment layout scatter) ----
    #pragma unroll
    for (int mt = 0; mt < 2; ++mt) {
        #pragma unroll
        for (int nt = 0; nt < 4; ++nt) {
            int row = wr * 32 + mt * 16 + g;
            int col = wc * 32 + nt * 8 + 2 * tig;
            float bx = b1s[col], by = b1s[col + 1];
            *(float2*)&sm.e.H[row * HSTR + col] =
                make_float2(fmaxf(acc[mt][nt][0] + bx, 0.f), fmaxf(acc[mt][nt][1] + by, 0.f));
            *(float2*)&sm.e.H[(row + 8) * HSTR + col] =
                make_float2(fmaxf(acc[mt][nt][2] + bx, 0.f), fmaxf(acc[mt][nt][3] + by, 0.f));
        }
    }
    __syncthreads();

    // ---- v = tanh(H @ W2 + b2): 2 threads per row, 8 outs each ----
    {
        int row  = t >> 1;
        int half = t & 1;
        float s[8];
        float4 bb0 = *(const float4*)&b2s[half * 8];
        float4 bb1 = *(const float4*)&b2s[half * 8 + 4];
        s[0]=bb0.x; s[1]=bb0.y; s[2]=bb0.z; s[3]=bb0.w;
        s[4]=bb1.x; s[5]=bb1.y; s[6]=bb1.z; s[7]=bb1.w;
        #pragma unroll 8
        for (int kk = 0; kk < 64; ++kk) {
            float h = sm.e.H[row * HSTR + kk];
            float4 w0 = *(const float4*)&W2s[kk * 16 + half * 8];
            float4 w1 = *(const float4*)&W2s[kk * 16 + half * 8 + 4];
            s[0]+=h*w0.x; s[1]+=h*w0.y; s[2]+=h*w0.z; s[3]+=h*w0.w;
            s[4]+=h*w1.x; s[5]+=h*w1.y; s[6]+=h*w1.z; s[7]+=h*w1.w;
        }
        float sq = 0.f;
        #pragma unroll
        for (int j = 0; j < 8; ++j) { s[j] = tanhf(s[j]); sq += s[j] * s[j]; }
        sq += __shfl_xor_sync(0xffffffffu, sq, 1);
        *(float4*)&sm.e.Vs[row * 16 + half * 8]     = make_float4(s[0], s[1], s[2], s[3]);
        *(float4*)&sm.e.Vs[row * 16 + half * 8 + 4] = make_float4(s[4], s[5], s[6], s[7]);
        if (half == 0) sm.e.ssq[row] = sq;
    }
    __syncthreads();

    // ---- fid = (va.vb)^2 / (|va|^2 |vb|^2), clipped ----
    if (t < 64) {
        float d = 0.f;
        #pragma unroll
        for (int j4 = 0; j4 < 4; ++j4) {
            float4 a = *(const float4*)&sm.e.Vs[t * 16 + j4 * 4];
            float4 b = *(const float4*)&sm.e.Vs[(t + 64) * 16 + j4 * 4];
            d += a.x * b.x + a.y * b.y + a.z * b.z + a.w * b.w;
        }
        float fid = (d * d) / (sm.e.ssq[t] * sm.e.ssq[t + 64]);
        out[p0 + t] = fminf(fmaxf(fid, 0.f), 1.f);
    }
}

extern "C" void kernel_launch(void* const* d_in, const int* in_sizes, int n_in,
                              void* d_out, int out_size)
{
    const float* img_a = (const float*)d_in[0];
    const float* img_b = (const float*)d_in[1];
    const float* W1    = (const float*)d_in[2];
    const float* b1    = (const float*)d_in[3];
    const float* W2    = (const float*)d_in[4];
    const float* b2    = (const float*)d_in[5];
    // d_in[6] = theta: unused — the circuit is unitary, fidelity is invariant.
    float* out = (float*)d_out;

    prep_w1<<<NCHUNK, 256>>>(W1);               // W1 -> per-chunk bf16 hi/lo tile images
    int blocks = out_size / 64;                 // 1024
    qcm_mma<<<blocks, 256>>>(img_a, img_b, b1, W2, b2, out);
}

// round 16
// speedup vs baseline: 1.0011x; 1.0011x over previous
#include <cuda_runtime.h>
#include <cuda_bf16.h>
#include <cstdint>

// fid[p] = clip( (va.vb)^2 / (|va|^2 |vb|^2), 0, 1 )
// va = tanh( relu(xa @ W1 + b1) @ W2 + b2 )   (quantum circuit is unitary -> cancels)
// GEMM1 via mma.sync m16n8k16 bf16 split hi/lo (3 MMAs). M=128/block, 8 warps, 32x32 tiles.
// A staged as RAW FP32 via cp.async (no LDG/convert/STS round-trip); hi/lo split happens in
// registers at fragment-load time. B tiles prepass-converted to smem images, contiguous cp.async.

#define KDIM   784
#define KC     16
#define NCHUNK 49
#define ASTR96 96      // A row stride bytes: 16 fp32 (64 B) + 32 pad -> quadrant-rotating, conflict-free
#define BSTRE  24      // B row stride in uint16 elems (48 B)
#define HSTR   66
#define BTILE  6144    // per-chunk B image: 3072 B hi + 3072 B lo

__device__ __align__(16) uint8_t g_W1B[NCHUNK * BTILE];

#define MMA(d, a, b) asm volatile( \
    "mma.sync.aligned.m16n8k16.row.col.f32.bf16.bf16.f32 " \
    "{%0,%1,%2,%3}, {%4,%5,%6,%7}, {%8,%9}, {%0,%1,%2,%3};" \
    : "+f"(d[0]), "+f"(d[1]), "+f"(d[2]), "+f"(d[3]) \
    : "r"(a[0]), "r"(a[1]), "r"(a[2]), "r"(a[3]), "r"(b[0]), "r"(b[1]))

__device__ __forceinline__ uint32_t bf2u(__nv_bfloat162 v) { return *(uint32_t*)&v; }

__device__ __forceinline__ uint32_t hi2(float x, float y, uint32_t& lo) {
    __nv_bfloat162 h = __float22bfloat162_rn(make_float2(x, y));
    __nv_bfloat162 l = __float22bfloat162_rn(make_float2(
        x - __bfloat162float(h.x), y - __bfloat162float(h.y)));
    lo = bf2u(l);
    return bf2u(h);
}

// float2 -> (hi bf16x2, lo bf16x2)
__device__ __forceinline__ uint32_t cvthl(float2 f, uint32_t& lo) {
    return hi2(f.x, f.y, lo);
}

__device__ __forceinline__ void cp16(uint32_t dst, const void* src) {
    asm volatile("cp.async.ca.shared.global [%0], [%1], 16;" :: "r"(dst), "l"(src));
}

// Per-chunk B tile images (identical to R10: row n = 16 bf16 at bytes [0,32) of a 48-B row).
__global__ void prep_w1(const float* __restrict__ W1) {
    int c = blockIdx.x;                 // 0..48
    int r = threadIdx.x;                // 0..255
    int n = r >> 2;
    int q = r & 3;
    int k = c * 16 + q * 4;
    float v0 = W1[(size_t)(k + 0) * 64 + n];
    float v1 = W1[(size_t)(k + 1) * 64 + n];
    float v2 = W1[(size_t)(k + 2) * 64 + n];
    float v3 = W1[(size_t)(k + 3) * 64 + n];
    uint32_t l0, l1;
    uint32_t h0 = hi2(v0, v1, l0);
    uint32_t h1 = hi2(v2, v3, l1);
    uint8_t* dst = g_W1B + (size_t)c * BTILE + n * 48 + q * 8;
    *(uint2*)dst          = make_uint2(h0, h1);
    *(uint2*)(dst + 3072) = make_uint2(l0, l1);
}

__global__ __launch_bounds__(256, 3)
void qcm_mma(const float* __restrict__ img_a,
             const float* __restrict__ img_b,
             const float* __restrict__ b1,
             const float* __restrict__ W2,
             const float* __restrict__ b2,
             float* __restrict__ out)
{
    __shared__ __align__(16) union {
        struct {
            uint8_t A[2][128 * ASTR96];    // 2 x 12288 B (fp32 rows, 96 B stride)
            uint8_t Bs[2][BTILE];          // 2 x 6144 B
        } m;                               // 36864 B
        struct {
            float H[128 * HSTR];
            float Vs[128 * 16];
            float ssq[128];
        } e;
    } sm;
    __shared__ float W2s[64 * 16];
    __shared__ float b1s[64];
    __shared__ float b2s[16];

    const int t    = threadIdx.x;
    const int lane = t & 31;
    const int wid  = t >> 5;
    const int wr   = wid >> 1;        // 0..3 : 32-row band
    const int wc   = wid & 1;         // 0..1 : 32-col half
    const int g    = lane >> 2;
    const int tig  = lane & 3;
    const int p0   = blockIdx.x * 64; // 64 pairs per block (128 rows)

    // params
    if (t < 64) b1s[t] = b1[t];
    if (t < 16) b2s[t] = b2[t];
    #pragma unroll
    for (int i = 0; i < 4; ++i) W2s[t + i * 256] = W2[t + i * 256];

    // A staging: 512 x 16B cp.async per chunk; thread t does 2 adjacent pieces of row t>>1
    const int arow = t >> 1;
    const int aq   = (t & 1) * 2;                 // piece index 0/2
    const float* abase = (arow < 64 ? img_a + (size_t)(p0 + arow) * KDIM
                                    : img_b + (size_t)(p0 + arow - 64) * KDIM) + aq * 4;
    const uint32_t sbA0 = (uint32_t)__cvta_generic_to_shared(sm.m.A[0]) + arow * ASTR96 + aq * 16;
    const uint32_t sbA1 = (uint32_t)__cvta_generic_to_shared(sm.m.A[1]) + arow * ASTR96 + aq * 16;
    const uint32_t sbB0 = (uint32_t)__cvta_generic_to_shared(sm.m.Bs[0]);
    const uint32_t sbB1 = (uint32_t)__cvta_generic_to_shared(sm.m.Bs[1]);

    float acc[2][4][4];
    #pragma unroll
    for (int mt = 0; mt < 2; ++mt)
        #pragma unroll
        for (int nt = 0; nt < 4; ++nt)
            #pragma unroll
            for (int j = 0; j < 4; ++j) acc[mt][nt][j] = 0.f;

    // ---- prologue: stage chunk 0 (all cp.async) ----
    {
        cp16(sbA0,      abase);
        cp16(sbA0 + 16, abase + 4);
        const uint8_t* src = g_W1B;
        cp16(sbB0 + t * 16, src + t * 16);
        if (t < 128) cp16(sbB0 + 4096 + t * 16, src + 4096 + t * 16);
        asm volatile("cp.async.commit_group;" ::: "memory");
        asm volatile("cp.async.wait_group 0;" ::: "memory");
    }
    __syncthreads();

    // ---- mainloop ----
    for (int c = 0; c < NCHUNK; ++c) {
        const int st = c & 1;
        const bool more = (c + 1 < NCHUNK);

        if (more) {
            const int k1 = (c + 1) * KC;
            const uint32_t dA = st ? sbA0 : sbA1;    // next buffer
            cp16(dA,      abase + k1);
            cp16(dA + 16, abase + k1 + 4);
            const uint8_t* src = g_W1B + (size_t)(c + 1) * BTILE;
            const uint32_t dB = st ? sbB0 : sbB1;
            cp16(dB + t * 16, src + t * 16);
            if (t < 128) cp16(dB + 4096 + t * 16, src + 4096 + t * 16);
            asm volatile("cp.async.commit_group;" ::: "memory");
        }

        const uint8_t*  As = sm.m.A[st];
        const uint16_t* Bh = (const uint16_t*)(sm.m.Bs[st]);
        const uint16_t* Bl = (const uint16_t*)(sm.m.Bs[st] + 3072);

        uint32_t bh[4][2], bl[4][2];
        #pragma unroll
        for (int nt = 0; nt < 4; ++nt) {
            int bb = (wc * 32 + nt * 8 + g) * BSTRE + 2 * tig;
            bh[nt][0] = *(const uint32_t*)&Bh[bb];
            bh[nt][1] = *(const uint32_t*)&Bh[bb + 8];
            bl[nt][0] = *(const uint32_t*)&Bl[bb];
            bl[nt][1] = *(const uint32_t*)&Bl[bb + 8];
        }

        #pragma unroll
        for (int mt = 0; mt < 2; ++mt) {
            const uint8_t* rbase = As + (wr * 32 + mt * 16 + g) * ASTR96 + tig * 8;
            float2 f0 = *(const float2*)(rbase);                    // row g,   k 2tig..2tig+1
            float2 f1 = *(const float2*)(rbase + 8 * ASTR96);       // row g+8
            float2 f2 = *(const float2*)(rbase + 32);               // row g,   k +8
            float2 f3 = *(const float2*)(rbase + 8 * ASTR96 + 32);  // row g+8, k +8
            uint32_t ah[4], al[4];
            ah[0] = cvthl(f0, al[0]);
            ah[1] = cvthl(f1, al[1]);
            ah[2] = cvthl(f2, al[2]);
            ah[3] = cvthl(f3, al[3]);
            #pragma unroll
            for (int nt = 0; nt < 4; ++nt) {
                MMA(acc[mt][nt], ah, bh[nt]);
                MMA(acc[mt][nt], ah, bl[nt]);
                MMA(acc[mt][nt], al, bh[nt]);
            }
        }

        asm volatile("cp.async.wait_group 0;" ::: "memory");
        __syncthreads();
    }

    // ---- epilogue: H = relu(acc + b1) into smem (fragment layout scatter) ----
    #pragma unroll
    for (int mt = 0; mt < 2; ++mt) {
        #pragma unroll
        for (int nt = 0; nt < 4; ++nt) {
            int row = wr * 32 + mt * 16 + g;
            int col = wc * 32 + nt * 8 + 2 * tig;
            float bx = b1s[col], by = b1s[col + 1];
            *(float2*)&sm.e.H[row * HSTR + col] =
                make_float2(fmaxf(acc[mt][nt][0] + bx, 0.f), fmaxf(acc[mt][nt][1] + by, 0.f));
            *(float2*)&sm.e.H[(row + 8) * HSTR + col] =
                make_float2(fmaxf(acc[mt][nt][2] + bx, 0.f), fmaxf(acc[mt][nt][3] + by, 0.f));
        }
    }
    __syncthreads();

    // ---- v = tanh(H @ W2 + b2): 2 threads per row, 8 outs each ----
    {
        int row  = t >> 1;
        int half = t & 1;
        float s[8];
        float4 bb0 = *(const float4*)&b2s[half * 8];
        float4 bb1 = *(const float4*)&b2s[half * 8 + 4];
        s[0]=bb0.x; s[1]=bb0.y; s[2]=bb0.z; s[3]=bb0.w;
        s[4]=bb1.x; s[5]=bb1.y; s[6]=bb1.z; s[7]=bb1.w;
        #pragma unroll 8
        for (int kk = 0; kk < 64; ++kk) {
            float h = sm.e.H[row * HSTR + kk];
            float4 w0 = *(const float4*)&W2s[kk * 16 + half * 8];
            float4 w1 = *(const float4*)&W2s[kk * 16 + half * 8 + 4];
            s[0]+=h*w0.x; s[1]+=h*w0.y; s[2]+=h*w0.z; s[3]+=h*w0.w;
            s[4]+=h*w1.x; s[5]+=h*w1.y; s[6]+=h*w1.z; s[7]+=h*w1.w;
        }
        float sq = 0.f;
        #pragma unroll
        for (int j = 0; j < 8; ++j) { s[j] = tanhf(s[j]); sq += s[j] * s[j]; }
        sq += __shfl_xor_sync(0xffffffffu, sq, 1);
        *(float4*)&sm.e.Vs[row * 16 + half * 8]     = make_float4(s[0], s[1], s[2], s[3]);
        *(float4*)&sm.e.Vs[row * 16 + half * 8 + 4] = make_float4(s[4], s[5], s[6], s[7]);
        if (half == 0) sm.e.ssq[row] = sq;
    }
    __syncthreads();

    // ---- fid = (va.vb)^2 / (|va|^2 |vb|^2), clipped ----
    if (t < 64) {
        float d = 0.f;
        #pragma unroll
        for (int j4 = 0; j4 < 4; ++j4) {
            float4 a = *(const float4*)&sm.e.Vs[t * 16 + j4 * 4];
            float4 b = *(const float4*)&sm.e.Vs[(t + 64) * 16 + j4 * 4];
            d += a.x * b.x + a.y * b.y + a.z * b.z + a.w * b.w;
        }
        float fid = (d * d) / (sm.e.ssq[t] * sm.e.ssq[t + 64]);
        out[p0 + t] = fminf(fmaxf(fid, 0.f), 1.f);
    }
}

extern "C" void kernel_launch(void* const* d_in, const int* in_sizes, int n_in,
                              void* d_out, int out_size)
{
    const float* img_a = (const float*)d_in[0];
    const float* img_b = (const float*)d_in[1];
    const float* W1    = (const float*)d_in[2];
    const float* b1    = (const float*)d_in[3];
    const float* W2    = (const float*)d_in[4];
    const float* b2    = (const float*)d_in[5];
    // d_in[6] = theta: unused — the circuit is unitary, fidelity is invariant.
    float* out = (float*)d_out;

    prep_w1<<<NCHUNK, 256>>>(W1);               // W1 -> per-chunk bf16 hi/lo tile images
    int blocks = out_size / 64;                 // 1024
    qcm_mma<<<blocks, 256>>>(img_a, img_b, b1, W2, b2, out);
}

// round 17
// speedup vs baseline: 1.0040x; 1.0029x over previous
#include <cuda_runtime.h>
#include <cuda_bf16.h>
#include <cstdint>

// fid[p] = clip( (va.vb)^2 / (|va|^2 |vb|^2), 0, 1 )
// va = tanh( relu(xa @ W1 + b1) @ W2 + b2 )   (quantum circuit is unitary -> cancels)
// GEMM1 via mma.sync m16n8k16 bf16 split hi/lo (3 MMAs). M=128/block, 8 warps, 32x32 tiles.
// A staged as RAW FP32 via cp.async (no LDG/convert/STS round-trip); hi/lo split happens in
// registers at fragment-load time. B tiles prepass-converted to smem images, contiguous cp.async.

#define KDIM   784
#define KC     16
#define NCHUNK 49
#define ASTR96 96      // A row stride bytes: 16 fp32 (64 B) + 32 pad -> quadrant-rotating, conflict-free
#define BSTRE  24      // B row stride in uint16 elems (48 B)
#define HSTR   66
#define BTILE  6144    // per-chunk B image: 3072 B hi + 3072 B lo

__device__ __align__(16) uint8_t g_W1B[NCHUNK * BTILE];

#define MMA(d, a, b) asm volatile( \
    "mma.sync.aligned.m16n8k16.row.col.f32.bf16.bf16.f32 " \
    "{%0,%1,%2,%3}, {%4,%5,%6,%7}, {%8,%9}, {%0,%1,%2,%3};" \
    : "+f"(d[0]), "+f"(d[1]), "+f"(d[2]), "+f"(d[3]) \
    : "r"(a[0]), "r"(a[1]), "r"(a[2]), "r"(a[3]), "r"(b[0]), "r"(b[1]))

__device__ __forceinline__ uint32_t bf2u(__nv_bfloat162 v) { return *(uint32_t*)&v; }

__device__ __forceinline__ uint32_t hi2(float x, float y, uint32_t& lo) {
    __nv_bfloat162 h = __float22bfloat162_rn(make_float2(x, y));
    __nv_bfloat162 l = __float22bfloat162_rn(make_float2(
        x - __bfloat162float(h.x), y - __bfloat162float(h.y)));
    lo = bf2u(l);
    return bf2u(h);
}

// float2 -> (hi bf16x2, lo bf16x2)
__device__ __forceinline__ uint32_t cvthl(float2 f, uint32_t& lo) {
    return hi2(f.x, f.y, lo);
}

__device__ __forceinline__ void cp16(uint32_t dst, const void* src) {
    asm volatile("cp.async.ca.shared.global [%0], [%1], 16;" :: "r"(dst), "l"(src));
}

// Per-chunk B tile images (identical to R10: row n = 16 bf16 at bytes [0,32) of a 48-B row).
__global__ void prep_w1(const float* __restrict__ W1) {
    int c = blockIdx.x;                 // 0..48
    int r = threadIdx.x;                // 0..255
    int n = r >> 2;
    int q = r & 3;
    int k = c * 16 + q * 4;
    float v0 = W1[(size_t)(k + 0) * 64 + n];
    float v1 = W1[(size_t)(k + 1) * 64 + n];
    float v2 = W1[(size_t)(k + 2) * 64 + n];
    float v3 = W1[(size_t)(k + 3) * 64 + n];
    uint32_t l0, l1;
    uint32_t h0 = hi2(v0, v1, l0);
    uint32_t h1 = hi2(v2, v3, l1);
    uint8_t* dst = g_W1B + (size_t)c * BTILE + n * 48 + q * 8;
    *(uint2*)dst          = make_uint2(h0, h1);
    *(uint2*)(dst + 3072) = make_uint2(l0, l1);
}

__global__ __launch_bounds__(256, 3)
void qcm_mma(const float* __restrict__ img_a,
             const float* __restrict__ img_b,
             const float* __restrict__ b1,
             const float* __restrict__ W2,
             const float* __restrict__ b2,
             float* __restrict__ out)
{
    __shared__ __align__(16) union {
        struct {
            uint8_t A[2][128 * ASTR96];    // 2 x 12288 B (fp32 rows, 96 B stride)
            uint8_t Bs[2][BTILE];          // 2 x 6144 B
        } m;                               // 36864 B
        struct {
            float H[128 * HSTR];
            float Vs[128 * 16];
            float ssq[128];
        } e;
    } sm;
    __shared__ float W2s[64 * 16];
    __shared__ float b1s[64];
    __shared__ float b2s[16];

    const int t    = threadIdx.x;
    const int lane = t & 31;
    const int wid  = t >> 5;
    const int wr   = wid >> 1;        // 0..3 : 32-row band
    const int wc   = wid & 1;         // 0..1 : 32-col half
    const int g    = lane >> 2;
    const int tig  = lane & 3;
    const int p0   = blockIdx.x * 64; // 64 pairs per block (128 rows)

    // params
    if (t < 64) b1s[t] = b1[t];
    if (t < 16) b2s[t] = b2[t];
    #pragma unroll
    for (int i = 0; i < 4; ++i) W2s[t + i * 256] = W2[t + i * 256];

    // A staging: 512 x 16B cp.async per chunk; thread t does 2 adjacent pieces of row t>>1
    const int arow = t >> 1;
    const int aq   = (t & 1) * 2;                 // piece index 0/2
    const float* abase = (arow < 64 ? img_a + (size_t)(p0 + arow) * KDIM
                                    : img_b + (size_t)(p0 + arow - 64) * KDIM) + aq * 4;
    const uint32_t sbA0 = (uint32_t)__cvta_generic_to_shared(sm.m.A[0]) + arow * ASTR96 + aq * 16;
    const uint32_t sbA1 = (uint32_t)__cvta_generic_to_shared(sm.m.A[1]) + arow * ASTR96 + aq * 16;
    const uint32_t sbB0 = (uint32_t)__cvta_generic_to_shared(sm.m.Bs[0]);
    const uint32_t sbB1 = (uint32_t)__cvta_generic_to_shared(sm.m.Bs[1]);

    float acc[2][4][4];
    #pragma unroll
    for (int mt = 0; mt < 2; ++mt)
        #pragma unroll
        for (int nt = 0; nt < 4; ++nt)
            #pragma unroll
            for (int j = 0; j < 4; ++j) acc[mt][nt][j] = 0.f;

    // ---- prologue: stage chunk 0 (all cp.async) ----
    {
        cp16(sbA0,      abase);
        cp16(sbA0 + 16, abase + 4);
        const uint8_t* src = g_W1B;
        cp16(sbB0 + t * 16, src + t * 16);
        if (t < 128) cp16(sbB0 + 4096 + t * 16, src + 4096 + t * 16);
        asm volatile("cp.async.commit_group;" ::: "memory");
        asm volatile("cp.async.wait_group 0;" ::: "memory");
    }
    __syncthreads();

    // ---- mainloop ----
    for (int c = 0; c < NCHUNK; ++c) {
        const int st = c & 1;
        const bool more = (c + 1 < NCHUNK);

        if (more) {
            const int k1 = (c + 1) * KC;
            const uint32_t dA = st ? sbA0 : sbA1;    // next buffer
            cp16(dA,      abase + k1);
            cp16(dA + 16, abase + k1 + 4);
            const uint8_t* src = g_W1B + (size_t)(c + 1) * BTILE;
            const uint32_t dB = st ? sbB0 : sbB1;
            cp16(dB + t * 16, src + t * 16);
            if (t < 128) cp16(dB + 4096 + t * 16, src + 4096 + t * 16);
            asm volatile("cp.async.commit_group;" ::: "memory");
        }

        const uint8_t*  As = sm.m.A[st];
        const uint16_t* Bh = (const uint16_t*)(sm.m.Bs[st]);
        const uint16_t* Bl = (const uint16_t*)(sm.m.Bs[st] + 3072);

        uint32_t bh[4][2], bl[4][2];
        #pragma unroll
        for (int nt = 0; nt < 4; ++nt) {
            int bb = (wc * 32 + nt * 8 + g) * BSTRE + 2 * tig;
            bh[nt][0] = *(const uint32_t*)&Bh[bb];
            bh[nt][1] = *(const uint32_t*)&Bh[bb + 8];
            bl[nt][0] = *(const uint32_t*)&Bl[bb];
            bl[nt][1] = *(const uint32_t*)&Bl[bb + 8];
        }

        #pragma unroll
        for (int mt = 0; mt < 2; ++mt) {
            const uint8_t* rbase = As + (wr * 32 + mt * 16 + g) * ASTR96 + tig * 8;
            float2 f0 = *(const float2*)(rbase);                    // row g,   k 2tig..2tig+1
            float2 f1 = *(const float2*)(rbase + 8 * ASTR96);       // row g+8
            float2 f2 = *(const float2*)(rbase + 32);               // row g,   k +8
            float2 f3 = *(const float2*)(rbase + 8 * ASTR96 + 32);  // row g+8, k +8
            uint32_t ah[4], al[4];
            ah[0] = cvthl(f0, al[0]);
            ah[1] = cvthl(f1, al[1]);
            ah[2] = cvthl(f2, al[2]);
            ah[3] = cvthl(f3, al[3]);
            #pragma unroll
            for (int nt = 0; nt < 4; ++nt) {
                MMA(acc[mt][nt], ah, bh[nt]);
                MMA(acc[mt][nt], ah, bl[nt]);
                MMA(acc[mt][nt], al, bh[nt]);
            }
        }

        asm volatile("cp.async.wait_group 0;" ::: "memory");
        __syncthreads();
    }

    // ---- epilogue: H = relu(acc + b1) into smem (fragment layout scatter) ----
    #pragma unroll
    for (int mt = 0; mt < 2; ++mt) {
        #pragma unroll
        for (int nt = 0; nt < 4; ++nt) {
            int row = wr * 32 + mt * 16 + g;
            int col = wc * 32 + nt * 8 + 2 * tig;
            float bx = b1s[col], by = b1s[col + 1];
            *(float2*)&sm.e.H[row * HSTR + col] =
                make_float2(fmaxf(acc[mt][nt][0] + bx, 0.f), fmaxf(acc[mt][nt][1] + by, 0.f));
            *(float2*)&sm.e.H[(row + 8) * HSTR + col] =
                make_float2(fmaxf(acc[mt][nt][2] + bx, 0.f), fmaxf(acc[mt][nt][3] + by, 0.f));
        }
    }
    __syncthreads();

    // ---- v = tanh(H @ W2 + b2): 2 threads per row, 8 outs each ----
    {
        int row  = t >> 1;
        int half = t & 1;
        float s[8];
        float4 bb0 = *(const float4*)&b2s[half * 8];
        float4 bb1 = *(const float4*)&b2s[half * 8 + 4];
        s[0]=bb0.x; s[1]=bb0.y; s[2]=bb0.z; s[3]=bb0.w;
        s[4]=bb1.x; s[5]=bb1.y; s[6]=bb1.z; s[7]=bb1.w;
        #pragma unroll 8
        for (int kk = 0; kk < 64; ++kk) {
            float h = sm.e.H[row * HSTR + kk];
            float4 w0 = *(const float4*)&W2s[kk * 16 + half * 8];
            float4 w1 = *(const float4*)&W2s[kk * 16 + half * 8 + 4];
            s[0]+=h*w0.x; s[1]+=h*w0.y; s[2]+=h*w0.z; s[3]+=h*w0.w;
            s[4]+=h*w1.x; s[5]+=h*w1.y; s[6]+=h*w1.z; s[7]+=h*w1.w;
        }
        float sq = 0.f;
        #pragma unroll
        for (int j = 0; j < 8; ++j) { s[j] = tanhf(s[j]); sq += s[j] * s[j]; }
        sq += __shfl_xor_sync(0xffffffffu, sq, 1);
        *(float4*)&sm.e.Vs[row * 16 + half * 8]     = make_float4(s[0], s[1], s[2], s[3]);
        *(float4*)&sm.e.Vs[row * 16 + half * 8 + 4] = make_float4(s[4], s[5], s[6], s[7]);
        if (half == 0) sm.e.ssq[row] = sq;
    }
    __syncthreads();

    // ---- fid = (va.vb)^2 / (|va|^2 |vb|^2), clipped ----
    if (t < 64) {
        float d = 0.f;
        #pragma unroll
        for (int j4 = 0; j4 < 4; ++j4) {
            float4 a = *(const float4*)&sm.e.Vs[t * 16 + j4 * 4];
            float4 b = *(const float4*)&sm.e.Vs[(t + 64) * 16 + j4 * 4];
            d += a.x * b.x + a.y * b.y + a.z * b.z + a.w * b.w;
        }
        float fid = (d * d) / (sm.e.ssq[t] * sm.e.ssq[t + 64]);
        out[p0 + t] = fminf(fmaxf(fid, 0.f), 1.f);
    }
}

extern "C" void kernel_launch(void* const* d_in, const int* in_sizes, int n_in,
                              void* d_out, int out_size)
{
    const float* img_a = (const float*)d_in[0];
    const float* img_b = (const float*)d_in[1];
    const float* W1    = (const float*)d_in[2];
    const float* b1    = (const float*)d_in[3];
    const float* W2    = (const float*)d_in[4];
    const float* b2    = (const float*)d_in[5];
    // d_in[6] = theta: unused — the circuit is unitary, fidelity is invariant.
    float* out = (float*)d_out;

    prep_w1<<<NCHUNK, 256>>>(W1);               // W1 -> per-chunk bf16 hi/lo tile images
    int blocks = out_size / 64;                 // 1024
    qcm_mma<<<blocks, 256>>>(img_a, img_b, b1, W2, b2, out);
}